// round 2
// baseline (speedup 1.0000x reference)
#include <cuda_runtime.h>
#include <cstdint>
#include <math.h>

#define T_STEPS 512
#define BATCH   64
#define IN0     256
#define HID     512
#define NBLK    128
#define NTHR    256
#define JPB     4     // hidden units per block

// -------- scratch (static device globals: no runtime allocation) --------
__device__ float g_hs[(size_t)T_STEPS * BATCH * HID];   // layer0 hidden outputs [T][B][H]
__device__ float g_hbuf[2 * BATCH * HID];               // double-buffered h
__device__ unsigned int          g_bar_count = 0;
__device__ volatile unsigned int g_bar_gen   = 0;

// -------- grid barrier (all 128 blocks guaranteed co-resident) --------
__device__ __forceinline__ void grid_barrier() {
    __syncthreads();
    if (threadIdx.x == 0) {
        unsigned int gen = g_bar_gen;
        __threadfence();
        if (atomicAdd(&g_bar_count, 1) == gridDim.x - 1) {
            g_bar_count = 0;
            __threadfence();
            g_bar_gen = gen + 1;
        } else {
            while (g_bar_gen == gen) { __nanosleep(64); }
        }
    }
    __syncthreads();
    __threadfence();
}

// -------- packed f32x2 helpers --------
__device__ __forceinline__ unsigned long long dupf(float v) {
    unsigned long long r;
    asm("mov.b64 %0, {%1, %1};" : "=l"(r) : "f"(v));
    return r;
}
__device__ __forceinline__ void fma2(unsigned long long &d, unsigned long long a, unsigned long long b) {
    asm("fma.rn.f32x2 %0, %1, %2, %0;" : "+l"(d) : "l"(a), "l"(b));
}
__device__ __forceinline__ void unpack2(unsigned long long v, float &lo, float &hi) {
    asm("mov.b64 {%0, %1}, %2;" : "=f"(lo), "=f"(hi) : "l"(v));
}

__device__ __forceinline__ float sigf(float x) {
    return 1.0f / (1.0f + __expf(-x));
}

// smem layout (floats):
//  w_s   [1024][16]  = 16384
//  h_s   [128][68]   =  8704   (k-major, padded pitch 68)
//  red_s [4][64][16] =  4096
//  c_s   [256]
//  bias_s[16]
#define SMEM_FLOATS (16384 + 8704 + 4096 + 256 + 16)

__global__ void __launch_bounds__(NTHR, 1)
lstm_scan_kernel(const float* __restrict__ inputs,
                 const float* __restrict__ h0,
                 const float* __restrict__ c0,
                 const float* __restrict__ w_ih0, const float* __restrict__ w_hh0,
                 const float* __restrict__ b_ih0, const float* __restrict__ b_hh0,
                 const float* __restrict__ w_ih1, const float* __restrict__ w_hh1,
                 const float* __restrict__ b_ih1, const float* __restrict__ b_hh1,
                 float* __restrict__ out)
{
    extern __shared__ float smem[];
    float* w_s    = smem;                 // [kglob][16]
    float* h_s    = w_s + 16384;          // [k][b], pitch 68
    float* red_s  = h_s + 8704;           // [kc][b][r]
    float* c_s    = red_s + 4096;         // [b*4+jj]
    float* bias_s = c_s + 256;            // [16]

    const int tid = threadIdx.x;
    const int bid = blockIdx.x;
    const int j0  = bid * JPB;

    const int kc    = tid >> 6;     // 0..3  split-K group
    const int inner = tid & 63;
    const int bb    = inner & 15;   // batch group: b = 4*bb + {0..3}
    const int rg    = inner >> 4;   // gate index: rows r = 4*rg + {0..3}

    for (int layer = 0; layer < 2; ++layer) {
        const int K_in  = layer ? HID : IN0;
        const int K_tot = K_in + HID;
        const float* w_ih = layer ? w_ih1 : w_ih0;
        const float* w_hh = layer ? w_hh1 : w_hh0;
        const float* b_ih = layer ? b_ih1 : b_ih0;
        const float* b_hh = layer ? b_hh1 : b_hh0;
        const float* xbase = layer ? (const float*)g_hs : inputs;
        const float* h0l = h0 + layer * BATCH * HID;
        const float* c0l = c0 + layer * BATCH * HID;

        // ---- per-layer init: weights+bias into smem, c state, h buffer 0 ----
        for (int e = tid; e < 16 * K_tot; e += NTHR) {
            int r  = e & 15;
            int kg = e >> 4;
            int row = ((r >> 2) * HID) + j0 + (r & 3);   // gate*H + j
            float v = (kg < K_in) ? w_ih[row * K_in + kg]
                                  : w_hh[row * HID + (kg - K_in)];
            w_s[kg * 16 + r] = v;
        }
        if (tid < 16) {
            int row = ((tid >> 2) * HID) + j0 + (tid & 3);
            bias_s[tid] = b_ih[row] + b_hh[row];
        }
        {
            int b = tid >> 2, jj = tid & 3;
            c_s[tid] = c0l[b * HID + j0 + jj];
            g_hbuf[b * HID + j0 + jj] = h0l[b * HID + j0 + jj];
        }
        grid_barrier();

        // ---- timestep scan ----
        for (int t = 0; t < T_STEPS; ++t) {
            const int cur = t & 1;
            const int nxt = cur ^ 1;
            const float* hcur = g_hbuf + cur * BATCH * HID;

            unsigned long long acc[8];
#pragma unroll
            for (int j = 0; j < 8; ++j) acc[j] = 0ull;

            for (int kb0 = 0; kb0 < K_tot; kb0 += 128) {
                // fill h_s[k][b] (transposed) from x_t or h_cur; chunks never straddle
                const bool  isx  = (kb0 < K_in);
                const float* src = isx ? (xbase + (size_t)t * BATCH * K_in) : hcur;
                const int   srcK = isx ? K_in : HID;
                const int   koff = isx ? kb0 : (kb0 - K_in);
#pragma unroll
                for (int it = 0; it < 2; ++it) {
                    int item = tid + it * NTHR;
                    int kq = item & 31, bq = item >> 5;
                    const float* s0 = src + (size_t)(4*bq) * srcK + koff + 4*kq;
                    float4 v0 = *(const float4*)(s0);
                    float4 v1 = *(const float4*)(s0 + srcK);
                    float4 v2 = *(const float4*)(s0 + 2*srcK);
                    float4 v3 = *(const float4*)(s0 + 3*srcK);
                    float* d = h_s + (4*kq) * 68 + 4*bq;
                    *(float4*)(d)        = make_float4(v0.x, v1.x, v2.x, v3.x);
                    *(float4*)(d + 68)   = make_float4(v0.y, v1.y, v2.y, v3.y);
                    *(float4*)(d + 136)  = make_float4(v0.z, v1.z, v2.z, v3.z);
                    *(float4*)(d + 204)  = make_float4(v0.w, v1.w, v2.w, v3.w);
                }
                __syncthreads();

                // accumulate: this thread's k-range within chunk = [kc*32, kc*32+32)
                const float* wp = w_s + (size_t)(kb0 + kc*32) * 16 + rg * 4;
                const float* hp = h_s + (kc*32) * 68 + 4*bb;
#pragma unroll 4
                for (int kk = 0; kk < 32; ++kk) {
                    ulonglong2 hv = *(const ulonglong2*)(hp + kk * 68);
                    float4     wv = *(const float4*)(wp + kk * 16);
                    unsigned long long w0 = dupf(wv.x), w1 = dupf(wv.y),
                                       w2 = dupf(wv.z), w3 = dupf(wv.w);
                    fma2(acc[0], hv.x, w0); fma2(acc[1], hv.x, w1);
                    fma2(acc[2], hv.x, w2); fma2(acc[3], hv.x, w3);
                    fma2(acc[4], hv.y, w0); fma2(acc[5], hv.y, w1);
                    fma2(acc[6], hv.y, w2); fma2(acc[7], hv.y, w3);
                }
                __syncthreads();
            }

            // write split-K partials
#pragma unroll
            for (int j = 0; j < 8; ++j) {
                float lo, hi; unpack2(acc[j], lo, hi);
                int b0 = 4*bb + 2*(j >> 2);
                int r  = rg*4 + (j & 3);
                red_s[kc*1024 + b0*16 + r]     = lo;
                red_s[kc*1024 + (b0+1)*16 + r] = hi;
            }
            __syncthreads();

            // gate update: thread -> (b, jj)
            {
                int b = tid >> 2, jj = tid & 3;
                int base = b*16 + jj;
                float gI = bias_s[jj]      + red_s[base]      + red_s[1024+base]      + red_s[2048+base]      + red_s[3072+base];
                float gF = bias_s[4+jj]    + red_s[base+4]    + red_s[1024+base+4]    + red_s[2048+base+4]    + red_s[3072+base+4];
                float gG = bias_s[8+jj]    + red_s[base+8]    + red_s[1024+base+8]    + red_s[2048+base+8]    + red_s[3072+base+8];
                float gO = bias_s[12+jj]   + red_s[base+12]   + red_s[1024+base+12]   + red_s[2048+base+12]   + red_s[3072+base+12];

                float ci = c_s[tid];
                float cn = sigf(gF) * ci + sigf(gI) * tanhf(gG);
                float hn = sigf(gO) * tanhf(cn);
                c_s[tid] = cn;

                int hidx = b * HID + j0 + jj;
                g_hbuf[nxt * BATCH * HID + hidx] = hn;
                if (layer == 0)
                    g_hs[((size_t)t * BATCH + b) * HID + j0 + jj] = hn;
                if (t == T_STEPS - 1) {
                    out[layer * BATCH * HID + hidx] = hn;                      // h_n
                    out[2 * BATCH * HID + layer * BATCH * HID + hidx] = cn;    // c_n
                }
            }
            grid_barrier();
        }
    }
}

// -------- passthrough copy: inputs -> out tail --------
__global__ void copy_inputs_kernel(const float4* __restrict__ src,
                                   float4* __restrict__ dst, int n4)
{
    int i = blockIdx.x * blockDim.x + threadIdx.x;
    int stride = gridDim.x * blockDim.x;
    for (; i < n4; i += stride) dst[i] = src[i];
}

extern "C" void kernel_launch(void* const* d_in, const int* in_sizes, int n_in,
                              void* d_out, int out_size)
{
    const float* inputs = (const float*)d_in[0];
    const float* h0     = (const float*)d_in[1];
    const float* c0     = (const float*)d_in[2];
    const float* w_ih0  = (const float*)d_in[3];
    const float* w_hh0  = (const float*)d_in[4];
    const float* b_ih0  = (const float*)d_in[5];
    const float* b_hh0  = (const float*)d_in[6];
    const float* w_ih1  = (const float*)d_in[7];
    const float* w_hh1  = (const float*)d_in[8];
    const float* b_ih1  = (const float*)d_in[9];
    const float* b_hh1  = (const float*)d_in[10];
    float* out = (float*)d_out;

    (void)in_sizes; (void)n_in; (void)out_size;

    cudaFuncSetAttribute(lstm_scan_kernel,
                         cudaFuncAttributeMaxDynamicSharedMemorySize,
                         SMEM_FLOATS * (int)sizeof(float));

    // passthrough: inputs occupy out[131072 ..]
    const int n_in_floats = T_STEPS * BATCH * IN0;      // 8388608
    copy_inputs_kernel<<<2048, 256>>>((const float4*)inputs,
                                      (float4*)(out + 2 * 2 * BATCH * HID),
                                      n_in_floats / 4);

    lstm_scan_kernel<<<NBLK, NTHR, SMEM_FLOATS * sizeof(float)>>>(
        inputs, h0, c0,
        w_ih0, w_hh0, b_ih0, b_hh0,
        w_ih1, w_hh1, b_ih1, b_hh1,
        out);
}

// round 3
// speedup vs baseline: 1.8172x; 1.8172x over previous
#include <cuda_runtime.h>
#include <cstdint>
#include <math.h>

#define T_STEPS 512
#define BATCH   64
#define IN0     256
#define HID     512
#define NBLK    128
#define NTHR    256
#define JPB     4     // hidden units per block -> 16 gate rows

// -------- static device scratch (no runtime allocation) --------
__device__ float g_hs[(size_t)T_STEPS * HID * BATCH];   // layer0 outputs, TRANSPOSED [t][k][b]
__device__ float g_xT[(size_t)T_STEPS * IN0 * BATCH];   // inputs transposed [t][k][b]
__device__ float g_hT[2 * HID * BATCH];                 // double-buffered h, [k][b]
__device__ unsigned g_arrive[NBLK];
__device__ unsigned g_release;
__device__ unsigned g_epoch;

// -------- packed f32x2 helpers --------
__device__ __forceinline__ unsigned long long dupf(float v) {
    unsigned long long r;
    asm("mov.b64 %0, {%1, %1};" : "=l"(r) : "f"(v));
    return r;
}
__device__ __forceinline__ void fma2(unsigned long long &d, unsigned long long a, unsigned long long b) {
    asm("fma.rn.f32x2 %0, %1, %2, %0;" : "+l"(d) : "l"(a), "l"(b));
}
__device__ __forceinline__ void unpack2(unsigned long long v, float &lo, float &hi) {
    asm("mov.b64 {%0, %1}, %2;" : "=f"(lo), "=f"(hi) : "l"(v));
}
__device__ __forceinline__ float sigf(float x) { return 1.0f / (1.0f + __expf(-x)); }

// -------- cp.async helpers --------
__device__ __forceinline__ void cp16(uint32_t sm, const float* g) {
    asm volatile("cp.async.cg.shared.global [%0], [%1], 16;" :: "r"(sm), "l"(g));
}
__device__ __forceinline__ void cp_commit() {
    asm volatile("cp.async.commit_group;" ::: "memory");
}
template<int N>
__device__ __forceinline__ void cp_wait() {
    asm volatile("cp.async.wait_group %0;" :: "n"(N) : "memory");
}

// one chunk = 128 k  x 64 b floats = 8192 floats = 32KB; 8 float4 per thread
__device__ __forceinline__ void issue_chunk(float* smdst, const float* src, int tid) {
    uint32_t s = (uint32_t)__cvta_generic_to_shared(smdst);
#pragma unroll
    for (int q = 0; q < 8; ++q) {
        int i4 = tid + q * NTHR;
        cp16(s + i4 * 16, src + i4 * 4);
    }
    cp_commit();
}

// -------- flag-based grid barrier (monotone gen across graph replays) --------
__device__ __forceinline__ void grid_barrier(unsigned gen) {
    __syncthreads();
    if (threadIdx.x == 0) {
        asm volatile("st.release.gpu.global.u32 [%0], %1;"
                     :: "l"(&g_arrive[blockIdx.x]), "r"(gen) : "memory");
    }
    if (blockIdx.x == 0) {
        if (threadIdx.x < NBLK) {
            unsigned v;
            do {
                asm volatile("ld.acquire.gpu.global.u32 %0, [%1];"
                             : "=r"(v) : "l"(&g_arrive[threadIdx.x]) : "memory");
            } while (v < gen);
        }
        __syncthreads();
        if (threadIdx.x == 0) {
            asm volatile("st.release.gpu.global.u32 [%0], %1;"
                         :: "l"(&g_release), "r"(gen) : "memory");
        }
    }
    if (threadIdx.x == 0) {
        unsigned v;
        do {
            asm volatile("ld.acquire.gpu.global.u32 %0, [%1];"
                         : "=r"(v) : "l"(&g_release) : "memory");
        } while (v < gen);
    }
    __syncthreads();
}

// smem layout (floats):
//  w_s   [1024][16]       = 16384
//  hbuf  3 x [128][64]    = 24576  (chunk ring, [k][b])
//  red_s [4][64][17]      =  4352  (padded pitch 17: conflict-free)
//  bias_s[16]
#define OFF_W    0
#define OFF_HBUF 16384
#define OFF_RED  (16384 + 24576)
#define OFF_BIAS (OFF_RED + 4352)
#define SMEM_FLOATS (OFF_BIAS + 16)

__global__ void __launch_bounds__(NTHR, 1)
lstm_scan_kernel(const float* __restrict__ h0,
                 const float* __restrict__ c0,
                 const float* __restrict__ w_ih0, const float* __restrict__ w_hh0,
                 const float* __restrict__ b_ih0, const float* __restrict__ b_hh0,
                 const float* __restrict__ w_ih1, const float* __restrict__ w_hh1,
                 const float* __restrict__ b_ih1, const float* __restrict__ b_hh1,
                 float* __restrict__ out)
{
    extern __shared__ float smem[];
    float* w_s    = smem + OFF_W;
    float* hbuf   = smem + OFF_HBUF;
    float* red_s  = smem + OFF_RED;
    float* bias_s = smem + OFF_BIAS;

    const int tid = threadIdx.x;
    const int bid = blockIdx.x;
    const int j0  = bid * JPB;

    // compute roles
    const int kc    = tid >> 6;      // 0..3 split-K
    const int inner = tid & 63;
    const int bb    = inner & 15;    // batches 4bb..4bb+3
    const int rg    = inner >> 4;    // rows rg*4..rg*4+3

    // gate roles
    const int jj = tid >> 6;         // 0..3
    const int b  = tid & 63;

    unsigned gen;
    {
        unsigned e;
        asm volatile("ld.global.u32 %0, [%1];" : "=r"(e) : "l"(&g_epoch));
        gen = e;  // same value in all blocks (written at end of previous launch)
    }

    float c_reg = 0.0f;

#pragma unroll
    for (int layer = 0; layer < 2; ++layer) {
        const int K_in  = layer ? HID : IN0;
        const int K_tot = K_in + HID;
        const int n_chunks = K_tot / 128;            // 6 or 8
        const float* w_ih = layer ? w_ih1 : w_ih0;
        const float* w_hh = layer ? w_hh1 : w_hh0;
        const float* b_ih = layer ? b_ih1 : b_ih0;
        const float* b_hh = layer ? b_hh1 : b_hh0;
        const float* xT   = layer ? (const float*)g_hs : (const float*)g_xT;
        const float* h0l  = h0 + layer * BATCH * HID;
        const float* c0l  = c0 + layer * BATCH * HID;

        // ---- init: weights (coalesced by row), bias, c, h0 ----
#pragma unroll 1
        for (int rr = 0; rr < 16; ++rr) {
            int row = (rr >> 2) * HID + j0 + (rr & 3);
            for (int kg = tid; kg < K_tot; kg += NTHR) {
                float v = (kg < K_in) ? w_ih[row * K_in + kg]
                                      : w_hh[row * HID + (kg - K_in)];
                w_s[kg * 16 + rr] = v;
            }
        }
        if (tid < 16) {
            int row = (tid >> 2) * HID + j0 + (tid & 3);
            bias_s[tid] = b_ih[row] + b_hh[row];
        }
        {
            int j = j0 + jj;
            c_reg = c0l[b * HID + j];
            g_hT[j * BATCH + b] = h0l[b * HID + j];   // buffer 0 (cur at t=0)
        }
        grid_barrier(++gen);

        // prefetch step-0 chunks 0,1 (x-sourced, ready)
        issue_chunk(hbuf + 0 * 8192, xT + 0, tid);
        issue_chunk(hbuf + 1 * 8192, xT + 128 * BATCH, tid);

        for (int t = 0; t < T_STEPS; ++t) {
            const int cur = t & 1;
            const int nxt = cur ^ 1;
            const float* hcur = g_hT + cur * HID * BATCH;
            const float* xt   = xT + (size_t)t * K_in * BATCH;

            unsigned long long acc[8];
#pragma unroll
            for (int j = 0; j < 8; ++j) acc[j] = 0ull;

#pragma unroll 1
            for (int c = 0; c < n_chunks; ++c) {
                // issue chunk c+2
                if (c + 2 < n_chunks) {
                    int kb0 = (c + 2) * 128;
                    const float* src = (kb0 < K_in) ? (xt + (size_t)kb0 * BATCH)
                                                    : (hcur + (size_t)(kb0 - K_in) * BATCH);
                    issue_chunk(hbuf + ((c + 2) % 3) * 8192, src, tid);
                    cp_wait<2>();
                } else if (c + 1 < n_chunks) {
                    cp_wait<1>();
                } else {
                    cp_wait<0>();
                }
                __syncthreads();

                // compute chunk c
                const float* hb = hbuf + (c % 3) * 8192 + kc * 32 * 64 + 4 * bb;
                const float* wp = w_s + (c * 128 + kc * 32) * 16 + rg * 4;
                ulonglong2 hv = *(const ulonglong2*)hb;
                float4     wv = *(const float4*)wp;
#pragma unroll
                for (int kk = 0; kk < 32; ++kk) {
                    ulonglong2 hvn = *(const ulonglong2*)(hb + (kk + 1) * 64);
                    float4     wvn = *(const float4*)(wp + (kk + 1) * 16);
                    unsigned long long w0 = dupf(wv.x), w1 = dupf(wv.y),
                                       w2 = dupf(wv.z), w3 = dupf(wv.w);
                    fma2(acc[0], hv.x, w0); fma2(acc[1], hv.x, w1);
                    fma2(acc[2], hv.x, w2); fma2(acc[3], hv.x, w3);
                    fma2(acc[4], hv.y, w0); fma2(acc[5], hv.y, w1);
                    fma2(acc[6], hv.y, w2); fma2(acc[7], hv.y, w3);
                    hv = hvn; wv = wvn;
                }
                __syncthreads();
            }

            // split-K partials -> red_s[kc][b][r], pitch 17
#pragma unroll
            for (int j = 0; j < 8; ++j) {
                float lo, hi; unpack2(acc[j], lo, hi);
                int bq = 4 * bb + 2 * (j >> 2);
                int r  = rg * 4 + (j & 3);
                red_s[(kc * 64 + bq)     * 17 + r] = lo;
                red_s[(kc * 64 + bq + 1) * 17 + r] = hi;
            }
            __syncthreads();

            // gates: thread -> (jj, b)
            {
                float s0, s1, s2, s3;
                {
                    int r;
                    r = jj;      s0 = bias_s[r] + red_s[b*17+r] + red_s[(64+b)*17+r] + red_s[(128+b)*17+r] + red_s[(192+b)*17+r];
                    r = 4 + jj;  s1 = bias_s[r] + red_s[b*17+r] + red_s[(64+b)*17+r] + red_s[(128+b)*17+r] + red_s[(192+b)*17+r];
                    r = 8 + jj;  s2 = bias_s[r] + red_s[b*17+r] + red_s[(64+b)*17+r] + red_s[(128+b)*17+r] + red_s[(192+b)*17+r];
                    r = 12 + jj; s3 = bias_s[r] + red_s[b*17+r] + red_s[(64+b)*17+r] + red_s[(128+b)*17+r] + red_s[(192+b)*17+r];
                }
                float cn = sigf(s1) * c_reg + sigf(s0) * tanhf(s2);
                float hn = sigf(s3) * tanhf(cn);
                c_reg = cn;

                int j = j0 + jj;
                g_hT[nxt * HID * BATCH + j * BATCH + b] = hn;
                if (layer == 0)
                    g_hs[((size_t)t * HID + j) * BATCH + b] = hn;
                if (t == T_STEPS - 1) {
                    out[layer * BATCH * HID + b * HID + j] = hn;                       // h_n
                    out[2 * BATCH * HID + layer * BATCH * HID + b * HID + j] = cn;     // c_n
                }
            }

            // prefetch next step's chunks 0,1 (x-sourced, independent of barrier)
            if (t + 1 < T_STEPS) {
                const float* xn = xT + (size_t)(t + 1) * K_in * BATCH;
                issue_chunk(hbuf + 0 * 8192, xn, tid);
                issue_chunk(hbuf + 1 * 8192, xn + 128 * BATCH, tid);
            }
            grid_barrier(++gen);
        }
    }

    // persist epoch for next graph replay (launches are stream-serialized)
    if (bid == 0 && tid == 0) {
        asm volatile("st.global.u32 [%0], %1;" :: "l"(&g_epoch), "r"(gen) : "memory");
    }
}

// -------- prepass: transpose inputs [T][B][I] -> g_xT [T][I][B] --------
__global__ void transpose_x_kernel(const float* __restrict__ in)
{
    __shared__ float tile[32][33];
    int t  = blockIdx.x;
    int i0 = blockIdx.y * 32;
    int b0 = blockIdx.z * 32;
    int tx = threadIdx.x, ty = threadIdx.y;   // 32 x 8
    const float* ip = in + (size_t)t * BATCH * IN0;
    float* op = g_xT + (size_t)t * IN0 * BATCH;
#pragma unroll
    for (int yy = 0; yy < 32; yy += 8)
        tile[ty + yy][tx] = ip[(b0 + ty + yy) * IN0 + i0 + tx];
    __syncthreads();
#pragma unroll
    for (int yy = 0; yy < 32; yy += 8)
        op[(i0 + ty + yy) * BATCH + b0 + tx] = tile[tx][ty + yy];
}

// -------- passthrough copy: inputs -> out tail --------
__global__ void copy_inputs_kernel(const float4* __restrict__ src,
                                   float4* __restrict__ dst, int n4)
{
    int i = blockIdx.x * blockDim.x + threadIdx.x;
    int stride = gridDim.x * blockDim.x;
    for (; i < n4; i += stride) dst[i] = src[i];
}

extern "C" void kernel_launch(void* const* d_in, const int* in_sizes, int n_in,
                              void* d_out, int out_size)
{
    const float* inputs = (const float*)d_in[0];
    const float* h0     = (const float*)d_in[1];
    const float* c0     = (const float*)d_in[2];
    const float* w_ih0  = (const float*)d_in[3];
    const float* w_hh0  = (const float*)d_in[4];
    const float* b_ih0  = (const float*)d_in[5];
    const float* b_hh0  = (const float*)d_in[6];
    const float* w_ih1  = (const float*)d_in[7];
    const float* w_hh1  = (const float*)d_in[8];
    const float* b_ih1  = (const float*)d_in[9];
    const float* b_hh1  = (const float*)d_in[10];
    float* out = (float*)d_out;

    (void)in_sizes; (void)n_in; (void)out_size;

    static int configured = 0;
    if (!configured) {
        cudaFuncSetAttribute(lstm_scan_kernel,
                             cudaFuncAttributeMaxDynamicSharedMemorySize,
                             SMEM_FLOATS * (int)sizeof(float));
        configured = 1;
    }

    // transpose inputs for the scan
    transpose_x_kernel<<<dim3(T_STEPS, IN0 / 32, BATCH / 32), dim3(32, 8)>>>(inputs);

    // passthrough: inputs occupy out[4*B*H ..]
    const int n_in_floats = T_STEPS * BATCH * IN0;
    copy_inputs_kernel<<<2048, 256>>>((const float4*)inputs,
                                      (float4*)(out + 4 * BATCH * HID),
                                      n_in_floats / 4);

    lstm_scan_kernel<<<NBLK, NTHR, SMEM_FLOATS * sizeof(float)>>>(
        h0, c0,
        w_ih0, w_hh0, b_ih0, b_hh0,
        w_ih1, w_hh1, b_ih1, b_hh1,
        out);
}

// round 4
// speedup vs baseline: 1.8997x; 1.0454x over previous
#include <cuda_runtime.h>
#include <cstdint>
#include <math.h>

#define T_STEPS 512
#define BATCH   64
#define IN0     256
#define HID     512
#define NBLK    128
#define NTHR    256
#define JPB     4     // hidden units per block -> 16 gate rows

// -------- static device scratch --------
__device__ float g_hs[(size_t)T_STEPS * HID * BATCH];   // layer0 outputs [t][k][b]
__device__ float g_xT[(size_t)T_STEPS * IN0 * BATCH];   // inputs transposed [t][k][b]
__device__ float g_hT[2 * HID * BATCH];                 // double-buffered h, [k][b]
__device__ unsigned g_prod[16];
__device__ unsigned g_cons[16];
__device__ unsigned g_fb;        // full-barrier counter (monotone forever)
__device__ unsigned g_fb_base;   // snapshot at end of previous launch

// -------- packed f32x2 helpers --------
__device__ __forceinline__ unsigned long long dupf(float v) {
    unsigned long long r;
    asm("mov.b64 %0, {%1, %1};" : "=l"(r) : "f"(v));
    return r;
}
__device__ __forceinline__ void fma2(unsigned long long &d, unsigned long long a, unsigned long long b) {
    asm("fma.rn.f32x2 %0, %1, %2, %0;" : "+l"(d) : "l"(a), "l"(b));
}
__device__ __forceinline__ void unpack2(unsigned long long v, float &lo, float &hi) {
    asm("mov.b64 {%0, %1}, %2;" : "=f"(lo), "=f"(hi) : "l"(v));
}
__device__ __forceinline__ float sigf(float x) { return 1.0f / (1.0f + __expf(-x)); }

// -------- sync primitives --------
__device__ __forceinline__ void arrive(unsigned* ctr) {
    asm volatile("red.release.gpu.global.add.u32 [%0], 1;" :: "l"(ctr) : "memory");
}
__device__ __forceinline__ void wait_ge(const unsigned* ctr, unsigned target) {
    unsigned v;
    do {
        asm volatile("ld.acquire.gpu.global.u32 %0, [%1];" : "=r"(v) : "l"(ctr) : "memory");
    } while ((int)(v - target) < 0);
}
// full barrier: each block +1; wait until base + n*NBLK
__device__ __forceinline__ void full_barrier(unsigned &expect) {
    __syncthreads();
    if (threadIdx.x == 0) {
        arrive(&g_fb);
        expect += NBLK;
        wait_ge(&g_fb, expect);
    }
    __syncthreads();
}

// -------- cp.async --------
__device__ __forceinline__ void cp16(uint32_t sm, const float* g) {
    asm volatile("cp.async.cg.shared.global [%0], [%1], 16;" :: "r"(sm), "l"(g));
}
__device__ __forceinline__ void cp_commit() { asm volatile("cp.async.commit_group;" ::: "memory"); }
template<int N>
__device__ __forceinline__ void cp_wait() { asm volatile("cp.async.wait_group %0;" :: "n"(N) : "memory"); }

// one chunk = 128k x 64b floats = 32KB; 8 float4 per thread
__device__ __forceinline__ void issue_chunk(float* smdst, const float* src, int tid) {
    uint32_t s = (uint32_t)__cvta_generic_to_shared(smdst);
#pragma unroll
    for (int q = 0; q < 8; ++q) {
        int i4 = tid + q * NTHR;
        cp16(s + i4 * 16, src + i4 * 4);
    }
    cp_commit();
}

// smem layout (floats)
#define OFF_W    0
#define OFF_HBUF 16384
#define OFF_RED  (16384 + 24576)
#define OFF_BIAS (OFF_RED + 4352)
#define SMEM_FLOATS (OFF_BIAS + 16)

// -------- inner chunk compute --------
__device__ __forceinline__ void compute_chunk(const float* hbuf_slot, const float* w_chunk,
                                              int kc, int bb, int rg,
                                              unsigned long long acc[8])
{
    const float* hb = hbuf_slot + kc * 32 * 64 + 4 * bb;
    const float* wp = w_chunk + (kc * 32) * 16 + rg * 4;
    ulonglong2 hv = *(const ulonglong2*)hb;
    float4     wv = *(const float4*)wp;
#pragma unroll
    for (int kk = 0; kk < 32; ++kk) {
        ulonglong2 hvn = *(const ulonglong2*)(hb + (kk + 1) * 64);
        float4     wvn = *(const float4*)(wp + (kk + 1) * 16);
        unsigned long long w0 = dupf(wv.x), w1 = dupf(wv.y),
                           w2 = dupf(wv.z), w3 = dupf(wv.w);
        fma2(acc[0], hv.x, w0); fma2(acc[1], hv.x, w1);
        fma2(acc[2], hv.x, w2); fma2(acc[3], hv.x, w3);
        fma2(acc[4], hv.y, w0); fma2(acc[5], hv.y, w1);
        fma2(acc[6], hv.y, w2); fma2(acc[7], hv.y, w3);
        hv = hvn; wv = wvn;
    }
}

template<int K_IN>
__device__ void run_layer(int layer, const float* __restrict__ xT,
                          const float* __restrict__ h0l, const float* __restrict__ c0l,
                          const float* __restrict__ w_ih, const float* __restrict__ w_hh,
                          const float* __restrict__ b_ih, const float* __restrict__ b_hh,
                          float* __restrict__ out, float* smem, unsigned &fb_expect)
{
    constexpr int XC = K_IN / 128;        // x chunks
    constexpr int K_TOT = K_IN + HID;

    float* w_s    = smem + OFF_W;
    float* hbuf   = smem + OFF_HBUF;
    float* red_s  = smem + OFF_RED;
    float* bias_s = smem + OFF_BIAS;

    const int tid = threadIdx.x;
    const int j0  = blockIdx.x * JPB;

    const int kc    = tid >> 6;
    const int inner = tid & 63;
    const int bb    = inner & 15;
    const int rg    = inner >> 4;
    const int jj    = tid >> 6;
    const int b     = tid & 63;

    // ---- init ----
    full_barrier(fb_expect);          // previous phase fully quiesced
    if (tid < 16) { g_prod[tid] = 0; g_cons[tid] = 0; }   // all blocks write 0: benign

#pragma unroll 1
    for (int rr = 0; rr < 16; ++rr) {
        int row = (rr >> 2) * HID + j0 + (rr & 3);
        for (int kg = tid; kg < K_TOT; kg += NTHR) {
            float v = (kg < K_IN) ? w_ih[row * K_IN + kg]
                                  : w_hh[row * HID + (kg - K_IN)];
            w_s[kg * 16 + rr] = v;
        }
    }
    if (tid < 16) {
        int row = (tid >> 2) * HID + j0 + (tid & 3);
        bias_s[tid] = b_ih[row] + b_hh[row];
    }
    float c_reg;
    {
        int j = j0 + jj;
        c_reg = c0l[b * HID + j];
        g_hT[j * BATCH + b] = h0l[b * HID + j];   // buffer 0
    }
    full_barrier(fb_expect);          // publish h0 + zeroed counters

    // prefetch step-0 x chunks
    issue_chunk(hbuf + 0 * 8192, xT + 0, tid);
    issue_chunk(hbuf + 1 * 8192, xT + (size_t)128 * BATCH, tid);

    for (int t = 0; t < T_STEPS; ++t) {
        const float* xt   = xT + (size_t)t * K_IN * BATCH;
        const float* hcur = g_hT + (t & 1) * HID * BATCH;

        unsigned long long acc[8];
#pragma unroll
        for (int j = 0; j < 8; ++j) acc[j] = 0ull;

        // ---- X phase: no inter-block sync needed ----
#pragma unroll
        for (int c = 0; c < XC; ++c) {
            if (c + 2 < XC) {
                issue_chunk(hbuf + ((c + 2) % 3) * 8192, xt + (size_t)(c + 2) * 128 * BATCH, tid);
                cp_wait<2>();
            } else if (c + 1 < XC) cp_wait<1>();
            else                   cp_wait<0>();
            __syncthreads();
            compute_chunk(hbuf + (c % 3) * 8192, w_s + c * 128 * 16, kc, bb, rg, acc);
            __syncthreads();
        }

        // ---- wait: all blocks produced h_t ----
        if (t > 0) {
            if (tid == 0) {
                unsigned target = 128u * ((unsigned)(t >> 4) + 1u) - (((t & 15) == 0) ? 128u : 0u);
                wait_ge(&g_prod[t & 15], target);
            }
            __syncthreads();
        }

        // ---- H phase ----
        issue_chunk(hbuf + ((XC + 0) % 3) * 8192, hcur + (size_t)0 * 128 * BATCH, tid);
        issue_chunk(hbuf + ((XC + 1) % 3) * 8192, hcur + (size_t)128 * BATCH, tid);
#pragma unroll
        for (int i = 0; i < 4; ++i) {
            if (i + 2 < 4) {
                issue_chunk(hbuf + ((XC + i + 2) % 3) * 8192, hcur + (size_t)(i + 2) * 128 * BATCH, tid);
                cp_wait<2>();
            } else if (i + 1 < 4) cp_wait<1>();
            else                  cp_wait<0>();
            __syncthreads();
            compute_chunk(hbuf + ((XC + i) % 3) * 8192, w_s + (XC + i) * 128 * 16, kc, bb, rg, acc);
            __syncthreads();
        }
        // all our reads of h_t done
        if (tid == 0) arrive(&g_cons[t & 15]);

        // ---- reduction ----
#pragma unroll
        for (int j = 0; j < 8; ++j) {
            float lo, hi; unpack2(acc[j], lo, hi);
            int bq = 4 * bb + 2 * (j >> 2);
            int r  = rg * 4 + (j & 3);
            red_s[(kc * 64 + bq)     * 17 + r] = lo;
            red_s[(kc * 64 + bq + 1) * 17 + r] = hi;
        }
        __syncthreads();

        float s0, s1, s2, s3;
        {
            int r;
            r = jj;      s0 = bias_s[r] + red_s[b*17+r] + red_s[(64+b)*17+r] + red_s[(128+b)*17+r] + red_s[(192+b)*17+r];
            r = 4 + jj;  s1 = bias_s[r] + red_s[b*17+r] + red_s[(64+b)*17+r] + red_s[(128+b)*17+r] + red_s[(192+b)*17+r];
            r = 8 + jj;  s2 = bias_s[r] + red_s[b*17+r] + red_s[(64+b)*17+r] + red_s[(128+b)*17+r] + red_s[(192+b)*17+r];
            r = 12 + jj; s3 = bias_s[r] + red_s[b*17+r] + red_s[(64+b)*17+r] + red_s[(128+b)*17+r] + red_s[(192+b)*17+r];
        }
        float cn = sigf(s1) * c_reg + sigf(s0) * tanhf(s2);
        float hn = sigf(s3) * tanhf(cn);
        c_reg = cn;

        // prefetch next step's x chunks (slots 0,1 free; overlaps the cons poll)
        if (t + 1 < T_STEPS) {
            const float* xn = xT + (size_t)(t + 1) * K_IN * BATCH;
            issue_chunk(hbuf + 0 * 8192, xn, tid);
            issue_chunk(hbuf + 1 * 8192, xn + (size_t)128 * BATCH, tid);
        }

        // ---- wait: everyone consumed h_{t-1} before we overwrite its buffer ----
        if (t >= 1) {
            if (tid == 0) {
                unsigned target = 128u * ((unsigned)((t - 1) >> 4) + 1u);
                wait_ge(&g_cons[(t - 1) & 15], target);
            }
            __syncthreads();
        }

        // ---- write h_{t+1} ----
        {
            int j = j0 + jj;
            g_hT[((t + 1) & 1) * HID * BATCH + j * BATCH + b] = hn;
            if (layer == 0)
                g_hs[((size_t)t * HID + j) * BATCH + b] = hn;
            if (t == T_STEPS - 1) {
                out[layer * BATCH * HID + b * HID + j] = hn;
                out[2 * BATCH * HID + layer * BATCH * HID + b * HID + j] = cn;
            }
        }
        __syncthreads();
        if (tid == 0) arrive(&g_prod[(t + 1) & 15]);
    }

    full_barrier(fb_expect);   // end-of-layer quiesce (also drains stray groups: all waited to 0)
}

__global__ void __launch_bounds__(NTHR, 1)
lstm_scan_kernel(const float* __restrict__ h0,
                 const float* __restrict__ c0,
                 const float* __restrict__ w_ih0, const float* __restrict__ w_hh0,
                 const float* __restrict__ b_ih0, const float* __restrict__ b_hh0,
                 const float* __restrict__ w_ih1, const float* __restrict__ w_hh1,
                 const float* __restrict__ b_ih1, const float* __restrict__ b_hh1,
                 float* __restrict__ out)
{
    extern __shared__ float smem[];
    unsigned fb_expect = g_fb_base;   // stable during this launch

    run_layer<IN0>(0, g_xT, h0, c0, w_ih0, w_hh0, b_ih0, b_hh0, out, smem, fb_expect);
    run_layer<HID>(1, g_hs, h0 + BATCH * HID, c0 + BATCH * HID,
                   w_ih1, w_hh1, b_ih1, b_hh1, out, smem, fb_expect);

    if (blockIdx.x == 0 && threadIdx.x == 0)
        g_fb_base = fb_expect;        // persist for next graph replay
}

// -------- prepass: transpose inputs to g_xT AND copy passthrough to out tail --------
__global__ void prep_kernel(const float* __restrict__ in, float* __restrict__ out_tail)
{
    __shared__ float tile[32][33];
    int t  = blockIdx.x;
    int i0 = blockIdx.y * 32;
    int b0 = blockIdx.z * 32;
    int tx = threadIdx.x, ty = threadIdx.y;   // 32 x 8
    const float* ip = in + (size_t)t * BATCH * IN0;
    float* cp = out_tail + (size_t)t * BATCH * IN0;
    float* op = g_xT + (size_t)t * IN0 * BATCH;
#pragma unroll
    for (int yy = 0; yy < 32; yy += 8) {
        float v = ip[(b0 + ty + yy) * IN0 + i0 + tx];
        tile[ty + yy][tx] = v;
        cp[(b0 + ty + yy) * IN0 + i0 + tx] = v;
    }
    __syncthreads();
#pragma unroll
    for (int yy = 0; yy < 32; yy += 8)
        op[(i0 + ty + yy) * BATCH + b0 + tx] = tile[tx][ty + yy];
}

extern "C" void kernel_launch(void* const* d_in, const int* in_sizes, int n_in,
                              void* d_out, int out_size)
{
    const float* inputs = (const float*)d_in[0];
    const float* h0     = (const float*)d_in[1];
    const float* c0     = (const float*)d_in[2];
    const float* w_ih0  = (const float*)d_in[3];
    const float* w_hh0  = (const float*)d_in[4];
    const float* b_ih0  = (const float*)d_in[5];
    const float* b_hh0  = (const float*)d_in[6];
    const float* w_ih1  = (const float*)d_in[7];
    const float* w_hh1  = (const float*)d_in[8];
    const float* b_ih1  = (const float*)d_in[9];
    const float* b_hh1  = (const float*)d_in[10];
    float* out = (float*)d_out;

    (void)in_sizes; (void)n_in; (void)out_size;

    cudaFuncSetAttribute(lstm_scan_kernel,
                         cudaFuncAttributeMaxDynamicSharedMemorySize,
                         SMEM_FLOATS * (int)sizeof(float));

    prep_kernel<<<dim3(T_STEPS, IN0 / 32, BATCH / 32), dim3(32, 8)>>>(
        inputs, out + 4 * BATCH * HID);

    lstm_scan_kernel<<<NBLK, NTHR, SMEM_FLOATS * sizeof(float)>>>(
        h0, c0,
        w_ih0, w_hh0, b_ih0, b_hh0,
        w_ih1, w_hh1, b_ih1, b_hh1,
        out);
}